// round 3
// baseline (speedup 1.0000x reference)
#include <cuda_runtime.h>

// DiscriminatorLoss: out = mean( (s==other_s ? +1 : -1) * x ), N = 33554432.
// HBM-bound streaming reduction (~402 MB read). Single fused kernel:
// 4-way-unrolled vec4 grid-stride loop (12 independent LDG.128 in flight,
// 4 independent accumulators), streaming loads (__ldcs), block reduce ->
// g_partials; last-arriving block (self-resetting atomicInc ticket) folds
// the 1024 partials in fixed order and writes the mean. Deterministic.

#define RBLOCKS 1024
#define RTHREADS 256

__device__ float g_partials[RBLOCKS];
__device__ unsigned int g_ticket;   // zero-initialized; wraps back to 0

__device__ __forceinline__ float dot_sel(int4 sv, int4 ov, float4 xv)
{
    float a = (sv.x == ov.x) ? xv.x : -xv.x;
    float b = (sv.y == ov.y) ? xv.y : -xv.y;
    float c = (sv.z == ov.z) ? xv.z : -xv.z;
    float d = (sv.w == ov.w) ? xv.w : -xv.w;
    return (a + b) + (c + d);
}

__global__ __launch_bounds__(RTHREADS)
void disc_loss_fused(const int* __restrict__ s,
                     const int* __restrict__ o,
                     const float* __restrict__ x,
                     int n4, float inv_n,
                     float* __restrict__ out)
{
    const int4*   s4 = reinterpret_cast<const int4*>(s);
    const int4*   o4 = reinterpret_cast<const int4*>(o);
    const float4* x4 = reinterpret_cast<const float4*>(x);

    const int stride = gridDim.x * blockDim.x;
    int i = blockIdx.x * blockDim.x + threadIdx.x;

    float acc0 = 0.0f, acc1 = 0.0f, acc2 = 0.0f, acc3 = 0.0f;

    // 4-way unroll: 12 independent 128-bit streaming loads per body.
    for (; i + 3 * stride < n4; i += 4 * stride) {
        int4   sa = __ldcs(&s4[i]);
        int4   sb = __ldcs(&s4[i +     stride]);
        int4   sc = __ldcs(&s4[i + 2 * stride]);
        int4   sd = __ldcs(&s4[i + 3 * stride]);
        int4   oa = __ldcs(&o4[i]);
        int4   ob = __ldcs(&o4[i +     stride]);
        int4   oc = __ldcs(&o4[i + 2 * stride]);
        int4   od = __ldcs(&o4[i + 3 * stride]);
        float4 xa = __ldcs(&x4[i]);
        float4 xb = __ldcs(&x4[i +     stride]);
        float4 xc = __ldcs(&x4[i + 2 * stride]);
        float4 xd = __ldcs(&x4[i + 3 * stride]);

        acc0 += dot_sel(sa, oa, xa);
        acc1 += dot_sel(sb, ob, xb);
        acc2 += dot_sel(sc, oc, xc);
        acc3 += dot_sel(sd, od, xd);
    }
    // Generic tail (unused on the bench shape: n4 == 32 * stride).
    for (; i < n4; i += stride) {
        int4   sv = __ldcs(&s4[i]);
        int4   ov = __ldcs(&o4[i]);
        float4 xv = __ldcs(&x4[i]);
        acc0 += dot_sel(sv, ov, xv);
    }

    float acc = (acc0 + acc1) + (acc2 + acc3);

    // Block reduce
    #pragma unroll
    for (int off = 16; off > 0; off >>= 1)
        acc += __shfl_xor_sync(0xffffffffu, acc, off);

    __shared__ float warp_sums[RTHREADS / 32];
    __shared__ bool  s_last;
    if ((threadIdx.x & 31) == 0)
        warp_sums[threadIdx.x >> 5] = acc;
    __syncthreads();

    if (threadIdx.x < 32) {
        float v = (threadIdx.x < (RTHREADS / 32)) ? warp_sums[threadIdx.x] : 0.0f;
        #pragma unroll
        for (int off = (RTHREADS / 64); off > 0; off >>= 1)
            v += __shfl_xor_sync(0xffffffffu, v, off);
        if (threadIdx.x == 0) {
            g_partials[blockIdx.x] = v;
            __threadfence();
            // atomicInc wraps: old==RBLOCKS-1 -> 0 (self-resets per replay).
            unsigned int t = atomicInc(&g_ticket, RBLOCKS - 1u);
            s_last = (t == RBLOCKS - 1u);
        }
    }
    __syncthreads();

    if (s_last) {
        // Fixed-order fold of all partials -> deterministic output.
        const volatile float* p = g_partials;
        float v = p[threadIdx.x]
                + p[threadIdx.x + 256]
                + p[threadIdx.x + 512]
                + p[threadIdx.x + 768];

        #pragma unroll
        for (int off = 16; off > 0; off >>= 1)
            v += __shfl_xor_sync(0xffffffffu, v, off);

        if ((threadIdx.x & 31) == 0)
            warp_sums[threadIdx.x >> 5] = v;
        __syncthreads();

        if (threadIdx.x < 32) {
            float t = (threadIdx.x < (RTHREADS / 32)) ? warp_sums[threadIdx.x] : 0.0f;
            #pragma unroll
            for (int off = (RTHREADS / 64); off > 0; off >>= 1)
                t += __shfl_xor_sync(0xffffffffu, t, off);
            if (threadIdx.x == 0)
                out[0] = t * inv_n;
        }
    }
}

extern "C" void kernel_launch(void* const* d_in, const int* in_sizes, int n_in,
                              void* d_out, int out_size)
{
    const int*   s = (const int*)d_in[0];
    const int*   o = (const int*)d_in[1];
    const float* x = (const float*)d_in[2];
    float* out = (float*)d_out;

    const int n  = in_sizes[0];
    const int n4 = n >> 2;

    disc_loss_fused<<<RBLOCKS, RTHREADS>>>(s, o, x, n4, 1.0f / (float)n, out);
}

// round 5
// speedup vs baseline: 1.0611x; 1.0611x over previous
#include <cuda_runtime.h>

// DiscriminatorLoss: out = mean( (s==other_s ? +1 : -1) * x ), N = 33554432.
// HBM-bound streaming reduction (~402 MB read). Single fused kernel.
// R2 structure (2-way unroll, 31 regs, 8-CTA/SM residency) but the grid is
// sized to exactly fill GB300's 152 SMs at full residency: 152*8 = 1216 CTAs
// (R2's 1024 left ~16% of warp slots empty -> occ 84%).
// Last-arriving block (self-resetting atomicInc ticket) folds partials in a
// fixed order and writes the mean. Deterministic.

#define RBLOCKS 1216          // 152 SMs * 8 CTAs/SM, one exactly-full wave
#define RTHREADS 256

__device__ float g_partials[RBLOCKS];
__device__ unsigned int g_ticket;   // zero-initialized; wraps back to 0

__global__ __launch_bounds__(RTHREADS)
void disc_loss_fused(const int* __restrict__ s,
                     const int* __restrict__ o,
                     const float* __restrict__ x,
                     int n4, float inv_n,
                     float* __restrict__ out)
{
    const int4*   s4 = reinterpret_cast<const int4*>(s);
    const int4*   o4 = reinterpret_cast<const int4*>(o);
    const float4* x4 = reinterpret_cast<const float4*>(x);

    float acc = 0.0f;
    const int stride = gridDim.x * blockDim.x;
    int i = blockIdx.x * blockDim.x + threadIdx.x;

    // 2-way unrolled grid-stride loop: 6 independent 128-bit loads in flight.
    for (; i + stride < n4; i += 2 * stride) {
        int4   sa = s4[i],          oa = o4[i];
        int4   sb = s4[i + stride], ob = o4[i + stride];
        float4 xa = x4[i];
        float4 xb = x4[i + stride];

        acc += (sa.x == oa.x) ? xa.x : -xa.x;
        acc += (sa.y == oa.y) ? xa.y : -xa.y;
        acc += (sa.z == oa.z) ? xa.z : -xa.z;
        acc += (sa.w == oa.w) ? xa.w : -xa.w;
        acc += (sb.x == ob.x) ? xb.x : -xb.x;
        acc += (sb.y == ob.y) ? xb.y : -xb.y;
        acc += (sb.z == ob.z) ? xb.z : -xb.z;
        acc += (sb.w == ob.w) ? xb.w : -xb.w;
    }
    for (; i < n4; i += stride) {
        int4   sv = s4[i], ov = o4[i];
        float4 xv = x4[i];
        acc += (sv.x == ov.x) ? xv.x : -xv.x;
        acc += (sv.y == ov.y) ? xv.y : -xv.y;
        acc += (sv.z == ov.z) ? xv.z : -xv.z;
        acc += (sv.w == ov.w) ? xv.w : -xv.w;
    }

    // Block reduce
    #pragma unroll
    for (int off = 16; off > 0; off >>= 1)
        acc += __shfl_xor_sync(0xffffffffu, acc, off);

    __shared__ float warp_sums[RTHREADS / 32];
    __shared__ bool  s_last;
    if ((threadIdx.x & 31) == 0)
        warp_sums[threadIdx.x >> 5] = acc;
    __syncthreads();

    if (threadIdx.x < 32) {
        float v = (threadIdx.x < (RTHREADS / 32)) ? warp_sums[threadIdx.x] : 0.0f;
        #pragma unroll
        for (int off = (RTHREADS / 64); off > 0; off >>= 1)
            v += __shfl_xor_sync(0xffffffffu, v, off);
        if (threadIdx.x == 0) {
            g_partials[blockIdx.x] = v;
            __threadfence();
            // atomicInc wraps: old==RBLOCKS-1 -> 0 (self-resets per replay).
            unsigned int t = atomicInc(&g_ticket, RBLOCKS - 1u);
            s_last = (t == RBLOCKS - 1u);
        }
    }
    __syncthreads();

    if (s_last) {
        // Fixed-order fold of all 1216 partials -> deterministic output.
        const volatile float* p = g_partials;
        float v = 0.0f;
        for (int j = threadIdx.x; j < RBLOCKS; j += RTHREADS)
            v += p[j];

        #pragma unroll
        for (int off = 16; off > 0; off >>= 1)
            v += __shfl_xor_sync(0xffffffffu, v, off);

        if ((threadIdx.x & 31) == 0)
            warp_sums[threadIdx.x >> 5] = v;
        __syncthreads();

        if (threadIdx.x < 32) {
            float t = (threadIdx.x < (RTHREADS / 32)) ? warp_sums[threadIdx.x] : 0.0f;
            #pragma unroll
            for (int off = (RTHREADS / 64); off > 0; off >>= 1)
                t += __shfl_xor_sync(0xffffffffu, t, off);
            if (threadIdx.x == 0)
                out[0] = t * inv_n;
        }
    }
}

extern "C" void kernel_launch(void* const* d_in, const int* in_sizes, int n_in,
                              void* d_out, int out_size)
{
    const int*   s = (const int*)d_in[0];
    const int*   o = (const int*)d_in[1];
    const float* x = (const float*)d_in[2];
    float* out = (float*)d_out;

    const int n  = in_sizes[0];
    const int n4 = n >> 2;

    disc_loss_fused<<<RBLOCKS, RTHREADS>>>(s, o, x, n4, 1.0f / (float)n, out);
}

// round 6
// speedup vs baseline: 1.1296x; 1.0645x over previous
#include <cuda_runtime.h>

// DiscriminatorLoss: out = mean( (s==other_s ? +1 : -1) * x ), N = 33554432.
// HBM-bound streaming reduction (~402 MB read).
// R2 shape restored (proven fastest: 1024 CTAs x 256 thr, 2-way unroll,
// 31 regs, n4/stride == 32 exactly -> zero tail, perfectly even work), plus
// __ldcs evict-first streaming loads (data is touched once; keep L2 as a
// staging buffer instead of polluting it).
// Last-arriving block (self-resetting atomicInc ticket) folds the partials
// in fixed order and writes the mean. Deterministic.

#define RBLOCKS 1024
#define RTHREADS 256

__device__ float g_partials[RBLOCKS];
__device__ unsigned int g_ticket;   // zero-initialized; wraps back to 0

__global__ __launch_bounds__(RTHREADS)
void disc_loss_fused(const int* __restrict__ s,
                     const int* __restrict__ o,
                     const float* __restrict__ x,
                     int n4, float inv_n,
                     float* __restrict__ out)
{
    const int4*   s4 = reinterpret_cast<const int4*>(s);
    const int4*   o4 = reinterpret_cast<const int4*>(o);
    const float4* x4 = reinterpret_cast<const float4*>(x);

    float acc = 0.0f;
    const int stride = gridDim.x * blockDim.x;
    int i = blockIdx.x * blockDim.x + threadIdx.x;

    // 2-way unrolled grid-stride loop: 6 independent 128-bit streaming loads
    // in flight per body. On the bench shape n4 == 32*stride: 16 clean bodies,
    // no tail.
    for (; i + stride < n4; i += 2 * stride) {
        int4   sa = __ldcs(&s4[i]);
        int4   oa = __ldcs(&o4[i]);
        int4   sb = __ldcs(&s4[i + stride]);
        int4   ob = __ldcs(&o4[i + stride]);
        float4 xa = __ldcs(&x4[i]);
        float4 xb = __ldcs(&x4[i + stride]);

        acc += (sa.x == oa.x) ? xa.x : -xa.x;
        acc += (sa.y == oa.y) ? xa.y : -xa.y;
        acc += (sa.z == oa.z) ? xa.z : -xa.z;
        acc += (sa.w == oa.w) ? xa.w : -xa.w;
        acc += (sb.x == ob.x) ? xb.x : -xb.x;
        acc += (sb.y == ob.y) ? xb.y : -xb.y;
        acc += (sb.z == ob.z) ? xb.z : -xb.z;
        acc += (sb.w == ob.w) ? xb.w : -xb.w;
    }
    for (; i < n4; i += stride) {
        int4   sv = __ldcs(&s4[i]);
        int4   ov = __ldcs(&o4[i]);
        float4 xv = __ldcs(&x4[i]);
        acc += (sv.x == ov.x) ? xv.x : -xv.x;
        acc += (sv.y == ov.y) ? xv.y : -xv.y;
        acc += (sv.z == ov.z) ? xv.z : -xv.z;
        acc += (sv.w == ov.w) ? xv.w : -xv.w;
    }

    // Block reduce
    #pragma unroll
    for (int off = 16; off > 0; off >>= 1)
        acc += __shfl_xor_sync(0xffffffffu, acc, off);

    __shared__ float warp_sums[RTHREADS / 32];
    __shared__ bool  s_last;
    if ((threadIdx.x & 31) == 0)
        warp_sums[threadIdx.x >> 5] = acc;
    __syncthreads();

    if (threadIdx.x < 32) {
        float v = (threadIdx.x < (RTHREADS / 32)) ? warp_sums[threadIdx.x] : 0.0f;
        #pragma unroll
        for (int off = (RTHREADS / 64); off > 0; off >>= 1)
            v += __shfl_xor_sync(0xffffffffu, v, off);
        if (threadIdx.x == 0) {
            g_partials[blockIdx.x] = v;
            __threadfence();
            // atomicInc wraps: old==RBLOCKS-1 -> 0 (self-resets per replay).
            unsigned int t = atomicInc(&g_ticket, RBLOCKS - 1u);
            s_last = (t == RBLOCKS - 1u);
        }
    }
    __syncthreads();

    if (s_last) {
        // Fixed-order fold of all partials -> deterministic output.
        const volatile float* p = g_partials;
        float v = p[threadIdx.x]
                + p[threadIdx.x + 256]
                + p[threadIdx.x + 512]
                + p[threadIdx.x + 768];

        #pragma unroll
        for (int off = 16; off > 0; off >>= 1)
            v += __shfl_xor_sync(0xffffffffu, v, off);

        if ((threadIdx.x & 31) == 0)
            warp_sums[threadIdx.x >> 5] = v;
        __syncthreads();

        if (threadIdx.x < 32) {
            float t = (threadIdx.x < (RTHREADS / 32)) ? warp_sums[threadIdx.x] : 0.0f;
            #pragma unroll
            for (int off = (RTHREADS / 64); off > 0; off >>= 1)
                t += __shfl_xor_sync(0xffffffffu, t, off);
            if (threadIdx.x == 0)
                out[0] = t * inv_n;
        }
    }
}

extern "C" void kernel_launch(void* const* d_in, const int* in_sizes, int n_in,
                              void* d_out, int out_size)
{
    const int*   s = (const int*)d_in[0];
    const int*   o = (const int*)d_in[1];
    const float* x = (const float*)d_in[2];
    float* out = (float*)d_out;

    const int n  = in_sizes[0];
    const int n4 = n >> 2;

    disc_loss_fused<<<RBLOCKS, RTHREADS>>>(s, o, x, n4, 1.0f / (float)n, out);
}